// round 16
// baseline (speedup 1.0000x reference)
#include <cuda_runtime.h>
#include <cuda_fp16.h>
#include <math.h>
#include <stdint.h>

// Problem constants (fixed: S=1024, B=16, I=D=1024, L=2)
#define S_LEN 1024
#define BATCH 16
#define DIM   1024
#define GDIM  (4 * DIM)       // 4096
#define KDIM  1024
#define MROWS (S_LEN * BATCH) // 16384
#define EPS 1e-6f
#define NPARTS 4
#define LANES (BATCH * DIM)   // 16384

// ---------------------------------------------------------------------------
// Device scratch (no allocation allowed in kernel_launch)
// ---------------------------------------------------------------------------
__device__ __half g_pre[(size_t)S_LEN * BATCH * GDIM];  // 134 MB (NO bias; fp16)
__device__ __half g_ah[(size_t)MROWS * KDIM];           // 33.5 MB (A in fp16)
__device__ __half g_wh0[(size_t)GDIM * KDIM];           // 8.4 MB  (W0 fp16)
__device__ __half g_wh1[(size_t)GDIM * KDIM];           // 8.4 MB  (W1 fp16)
__device__ float  g_state[4 * LANES];                   // scan h,c,n,m handoff

// ---------------------------------------------------------------------------
// Host-side stream/events for intra-capture pipelining. Created in a static
// initializer (before the harness's memory checkpoints; no device-memory
// delta during the run). kernel_launch records the SAME launch DAG on every
// call — fully deterministic.
// ---------------------------------------------------------------------------
static cudaStream_t g_s2;
static cudaEvent_t  g_evFork;
static cudaEvent_t  g_evS0[NPARTS];
static cudaEvent_t  g_evG1[NPARTS];
static int g_init_dummy = [](){
    cudaStreamCreateWithFlags(&g_s2, cudaStreamNonBlocking);
    cudaEventCreateWithFlags(&g_evFork, cudaEventDisableTiming);
    for (int i = 0; i < NPARTS; i++) {
        cudaEventCreateWithFlags(&g_evS0[i], cudaEventDisableTiming);
        cudaEventCreateWithFlags(&g_evG1[i], cudaEventDisableTiming);
    }
    return 0;
}();

// ---------------------------------------------------------------------------
// PTX helpers — base-target only (NO tcgen05: harness emits compute_103 PTX)
// ---------------------------------------------------------------------------
__device__ __forceinline__ uint32_t smem_u32(const void* p) {
    uint32_t a;
    asm("{ .reg .u64 t; cvta.to.shared.u64 t, %1; cvt.u32.u64 %0, t; }"
        : "=r"(a) : "l"(p));
    return a;
}
__device__ __forceinline__ void cp16(uint32_t dst, const void* src) {
    asm volatile("cp.async.cg.shared.global [%0], [%1], 16;"
                 :: "r"(dst), "l"(src));
}
__device__ __forceinline__ void ldsm_x4(uint32_t& r0, uint32_t& r1,
                                        uint32_t& r2, uint32_t& r3,
                                        uint32_t addr) {
    asm volatile("ldmatrix.sync.aligned.m8n8.x4.shared.b16 {%0,%1,%2,%3}, [%4];"
                 : "=r"(r0), "=r"(r1), "=r"(r2), "=r"(r3) : "r"(addr));
}
__device__ __forceinline__ void mma_f16(float* d, const uint32_t* a,
                                        uint32_t b0, uint32_t b1) {
    asm volatile(
        "mma.sync.aligned.m16n8k16.row.col.f32.f16.f16.f32 "
        "{%0,%1,%2,%3}, {%4,%5,%6,%7}, {%8,%9}, {%0,%1,%2,%3};"
        : "+f"(d[0]), "+f"(d[1]), "+f"(d[2]), "+f"(d[3])
        : "r"(a[0]), "r"(a[1]), "r"(a[2]), "r"(a[3]), "r"(b0), "r"(b1));
}

// Fast math (rel err ~2^-21; far under the 1e-3 budget)
__device__ __forceinline__ float fast_tanh(float x) {
    float e = __expf(2.0f * x);
    return __fdividef(e - 1.0f, e + 1.0f);
}

// Swizzle: rows are 64B (32 fp16); XOR the 16B-segment index with (row>>1)&3
__device__ __forceinline__ uint32_t swz_addr(uint32_t plane_base, int row, int seg) {
    return plane_base + (uint32_t)(row * 64) + ((uint32_t)((seg ^ ((row >> 1) & 3)) << 4));
}

// ---------------------------------------------------------------------------
// Generic fp32 -> fp16 convert (grid = n/1024 blocks of 256 threads).
// ---------------------------------------------------------------------------
#define NA_BLOCKS (MROWS * KDIM / 1024)   // 16384
#define NW_BLOCKS (GDIM * KDIM / 1024)    // 4096

__global__ __launch_bounds__(256)
void convert_kernel(const float* __restrict__ src, __half* __restrict__ dst)
{
    int i = (blockIdx.x * 256 + threadIdx.x) * 4;
    float4 v = __ldcs(reinterpret_cast<const float4*>(src + i));
    __half2* d2 = reinterpret_cast<__half2*>(dst + i);
    d2[0] = __half2(__float2half(v.x), __float2half(v.y));
    d2[1] = __half2(__float2half(v.z), __float2half(v.w));
}

// ---------------------------------------------------------------------------
// HMMA GEMM (R11/R14 best config — DO NOT PERTURB): C[M,N] = A @ W^T, fp16
// in/out, fp32 accum, NO bias. CTA 128x128, 4 warps (2Mx2N, 64x64 warp
// tiles), 128-thr CTAs, 2 CTAs/SM. K-chunk 32, 4-stage cp.async pipeline.
// bm_base selects an M-slice (grid.y = slice height / 128).
// ---------------------------------------------------------------------------
#define KCHUNK 32
#define NCHUNK (KDIM / KCHUNK)       // 32
#define PLANE  8192                  // 128 rows * 64 bytes
#define STAGE_BYTES (2 * PLANE)      // [A, W] = 16 KB
#define STAGES 4
#define GEMM_SMEM (STAGES * STAGE_BYTES)   // 64 KB

__device__ __forceinline__ void load_chunk(uint32_t stage_base,
                                           const __half* Ap,
                                           const __half* Wp,
                                           int k0, int tid)
{
#pragma unroll
    for (int p = 0; p < 2; p++) {
        const __half* src = (p == 0) ? Ap : Wp;
#pragma unroll
        for (int h = 0; h < 4; h++) {
            int it = tid + h * 128;          // 0..511
            int row = it >> 2;
            int seg = it & 3;
            cp16(swz_addr(stage_base + p * PLANE, row, seg),
                 src + (size_t)row * KDIM + k0 + seg * 8);
        }
    }
}

__global__ __launch_bounds__(128, 2)
void gemm_tc_kernel(const __half* __restrict__ Ah,
                    const __half* __restrict__ Wh,
                    __half* __restrict__ C,
                    int bm_base)
{
    extern __shared__ __align__(1024) char smem[];
    const uint32_t sbase = smem_u32(smem);
    const int tid  = threadIdx.x;
    const int wid  = tid >> 5;      // 0..3
    const int lane = tid & 31;
    const int warp_m = wid & 1;     // 2 warps in M: 64 rows each
    const int warp_n = wid >> 1;    // 2 warps in N: 64 cols each
    const int bm = bm_base + blockIdx.y * 128;
    const int bn = blockIdx.x * 128;

    const __half* Ap = Ah + (size_t)bm * KDIM;
    const __half* Wp = Wh + (size_t)bn * KDIM;

    float acc[4][8][4];
#pragma unroll
    for (int i = 0; i < 4; i++)
#pragma unroll
        for (int j = 0; j < 8; j++)
#pragma unroll
            for (int k = 0; k < 4; k++) acc[i][j][k] = 0.0f;

    // Prologue: stages 0,1,2
    load_chunk(sbase + 0 * STAGE_BYTES, Ap, Wp, 0 * KCHUNK, tid);
    asm volatile("cp.async.commit_group;");
    load_chunk(sbase + 1 * STAGE_BYTES, Ap, Wp, 1 * KCHUNK, tid);
    asm volatile("cp.async.commit_group;");
    load_chunk(sbase + 2 * STAGE_BYTES, Ap, Wp, 2 * KCHUNK, tid);
    asm volatile("cp.async.commit_group;");

    const int a_lrow = lane & 15;
    const int a_lseg = lane >> 4;
    const int b_lrow = (lane & 7) + ((lane >> 4) << 3);
    const int b_lseg = (lane >> 3) & 1;

    for (int i = 0; i < NCHUNK; i++) {
        const int rem = NCHUNK - 1 - i;
        if (rem >= 2)      { asm volatile("cp.async.wait_group 2;"); }
        else if (rem == 1) { asm volatile("cp.async.wait_group 1;"); }
        else               { asm volatile("cp.async.wait_group 0;"); }
        __syncthreads();

        if (i + 3 < NCHUNK) {
            load_chunk(sbase + (uint32_t)((i + 3) % STAGES) * STAGE_BYTES,
                       Ap, Wp, (i + 3) * KCHUNK, tid);
            asm volatile("cp.async.commit_group;");
        }

        const uint32_t st = sbase + (uint32_t)(i % STAGES) * STAGE_BYTES;
        const uint32_t base_a = st;
        const uint32_t base_w = st + PLANE;

#pragma unroll
        for (int ks = 0; ks < 2; ks++) {
            uint32_t a[4][4], w[4][4];
#pragma unroll
            for (int jj = 0; jj < 4; jj++) {
                int row = warp_n * 64 + jj * 16 + b_lrow;
                ldsm_x4(w[jj][0], w[jj][1], w[jj][2], w[jj][3],
                        swz_addr(base_w, row, ks * 2 + b_lseg));
            }
#pragma unroll
            for (int ti = 0; ti < 4; ti++) {
                int row = warp_m * 64 + ti * 16 + a_lrow;
                ldsm_x4(a[ti][0], a[ti][1], a[ti][2], a[ti][3],
                        swz_addr(base_a, row, ks * 2 + a_lseg));
            }
#pragma unroll
            for (int ti = 0; ti < 4; ti++)
#pragma unroll
                for (int jj = 0; jj < 4; jj++) {
                    mma_f16(acc[ti][2 * jj + 0], a[ti], w[jj][0], w[jj][1]);
                    mma_f16(acc[ti][2 * jj + 1], a[ti], w[jj][2], w[jj][3]);
                }
        }
    }

    // Epilogue: fp16 streaming stores (C read once by the scan; 134MB)
    const int mrow0 = bm + warp_m * 64 + (lane >> 2);
    const int col0  = bn + warp_n * 64 + (lane & 3) * 2;
#pragma unroll
    for (int ti = 0; ti < 4; ti++) {
        const int r0 = mrow0 + ti * 16;
#pragma unroll
        for (int g = 0; g < 8; g++) {
            int col = col0 + g * 8;
            __half2 v0 = __floats2half2_rn(acc[ti][g][0], acc[ti][g][1]);
            __half2 v1 = __floats2half2_rn(acc[ti][g][2], acc[ti][g][3]);
            __stcs(reinterpret_cast<__half2*>(C + (size_t)r0 * GDIM + col), v0);
            __stcs(reinterpret_cast<__half2*>(C + (size_t)(r0 + 8) * GDIM + col), v1);
        }
    }
}

// ---------------------------------------------------------------------------
// Elementwise sLSTM scan PART: processes 256 timesteps (16 chunks of 16).
// part==0 loads state from h0/extra0; else from g_state. part==NPARTS-1
// writes hf/extraf; else g_state. fp16 pre (bias-free) staged via cp.async,
// quad buffered; bias added in fp32; R15 MUFU reductions retained.
// EMIT_HALF: layer-0 writes h as fp16 into ah (GEMM1's A operand).
// ---------------------------------------------------------------------------
#define CH 16
#define NP 16          // chunks per part (16 * 16 steps = 256 timesteps)
#define SBUF 4

template <bool EMIT_HALF>
__global__ __launch_bounds__(64)
void slstm_scan_kernel(const __half* __restrict__ pre,    // [S,B,4D] (no bias)
                       const float* __restrict__ bias,    // [4D]
                       const float* __restrict__ r,       // [4D]
                       const float* __restrict__ h0,      // [L,B,D]
                       const float* __restrict__ extra0,  // [L,B,3D]
                       int layer, int part,
                       float* __restrict__ out_f32,       // [S,B,D] (or null)
                       __half* __restrict__ out_h16,      // [S,B,D] (or null)
                       float* __restrict__ hf,            // [L,B,D]
                       float* __restrict__ extraf,        // [L,B,3D]
                       float* __restrict__ state)         // [4][LANES]
{
    __shared__ __half buf[SBUF][CH][4][64];   // 8 KB

    const int ltid = threadIdx.x;                 // 0..63
    const int L0 = blockIdx.x * 64;               // lane base (all same b)
    const int b  = L0 >> 10;
    const int d0 = L0 & (DIM - 1);
    const int d  = d0 + ltid;
    const int idx = L0 + ltid;                    // global lane 0..16383

    const float rz = r[0 * DIM + d];
    const float ri = r[1 * DIM + d];
    const float rf = r[2 * DIM + d];
    const float ro = r[3 * DIM + d];
    const float bz = bias[0 * DIM + d];
    const float bi = bias[1 * DIM + d];
    const float bf = bias[2 * DIM + d];
    const float bo = bias[3 * DIM + d];
    const bool rzero = (rz == 0.0f) && (ri == 0.0f) && (rf == 0.0f) && (ro == 0.0f);

    const size_t lbd  = (size_t)layer * BATCH * DIM + (size_t)b * DIM;
    const size_t lb3d = (size_t)layer * BATCH * 3 * DIM + (size_t)b * 3 * DIM;

    float h, c, n, m;
    if (part == 0) {
        h = h0[lbd + d];
        c = extra0[lb3d + 0 * DIM + d];
        n = extra0[lb3d + 1 * DIM + d];
        m = extra0[lb3d + 2 * DIM + d];
    } else {
        h = state[0 * LANES + idx];
        c = state[1 * LANES + idx];
        n = state[2 * LANES + idx];
        m = state[3 * LANES + idx];
    }

    // Prefetch mapping: g = gate (0..3), cc = 16B chunk (0..7), sh = parity.
    const int g  = ltid >> 4;
    const int cc = ltid & 7;
    const int sh = (ltid >> 3) & 1;
    const size_t strideT = (size_t)BATCH * GDIM;
    const __half* src0 = pre + (size_t)b * GDIM + (size_t)g * DIM + d0 + cc * 8;

#define SCAN_PREFETCH(stage, k)                                               \
    do {                                                                      \
        const __half* _s = src0 + ((size_t)(k) * CH + sh) * strideT;          \
        _Pragma("unroll")                                                     \
        for (int _jj = 0; _jj < CH / 2; _jj++) {                              \
            cp16(smem_u32(&buf[stage][2 * _jj + sh][g][cc * 8]), _s);         \
            _s += 2 * strideT;                                                \
        }                                                                     \
        asm volatile("cp.async.commit_group;");                               \
    } while (0)

    const int K0 = part * NP;   // global chunk base
    SCAN_PREFETCH(0, K0 + 0);
    SCAN_PREFETCH(1, K0 + 1);
    SCAN_PREFETCH(2, K0 + 2);
    SCAN_PREFETCH(3, K0 + 3);

    const size_t strideO = (size_t)BATCH * DIM;
    size_t outIdx = (size_t)b * DIM + d + (size_t)K0 * CH * strideO;

    for (int kk = 0; kk < NP; kk++) {
        if (kk + 3 < NP)      { asm volatile("cp.async.wait_group 3;"); }
        else if (kk + 2 < NP) { asm volatile("cp.async.wait_group 2;"); }
        else if (kk + 1 < NP) { asm volatile("cp.async.wait_group 1;"); }
        else                  { asm volatile("cp.async.wait_group 0;"); }
        __syncthreads();

        const int cur = kk % SBUF;

        if (rzero) {
            float zt[CH], den[CH];
#pragma unroll
            for (int j = 0; j < CH; j++) {
                zt[j]  = fast_tanh(__half2float(buf[cur][j][0][ltid]) + bz);
                den[j] = 1.0f + __expf(-(__half2float(buf[cur][j][3][ltid]) + bo));
            }
#pragma unroll
            for (int j = 0; j < CH; j++) {
                const float ip = __half2float(buf[cur][j][1][ltid]) + bi;
                const float fm = __half2float(buf[cur][j][2][ltid]) + bf + m;
                const float mn = fmaxf(fm, ip);
                const float e  = __expf(fminf(fm, ip) - mn);
                const bool ffl = fm >= ip;
                const float ft = ffl ? 1.0f : e;
                const float it = ffl ? e : 1.0f;
                c = ft * c + it * zt[j];
                n = ft * n + it;
                m = mn;
                h = __fdividef(c, den[j] * (fabsf(n) + EPS));
                if (EMIT_HALF) out_h16[outIdx] = __float2half(h);
                else           __stcs(out_f32 + outIdx, h);
                outIdx += strideO;
            }
        } else {
#pragma unroll
            for (int j = 0; j < CH; j++) {
                const float zp = __half2float(buf[cur][j][0][ltid]) + bz + rz * h;
                const float ip = __half2float(buf[cur][j][1][ltid]) + bi + ri * h;
                const float fp = __half2float(buf[cur][j][2][ltid]) + bf + rf * h;
                const float op = __half2float(buf[cur][j][3][ltid]) + bo + ro * h;
                const float zt  = fast_tanh(zp);
                const float den = 1.0f + __expf(-op);
                const float fm = fp + m;
                const float mn = fmaxf(fm, ip);
                const float e  = __expf(fminf(fm, ip) - mn);
                const bool ffl = fm >= ip;
                const float ft = ffl ? 1.0f : e;
                const float it = ffl ? e : 1.0f;
                c = ft * c + it * zt;
                n = ft * n + it;
                m = mn;
                h = __fdividef(c, den * (fabsf(n) + EPS));
                if (EMIT_HALF) out_h16[outIdx] = __float2half(h);
                else           __stcs(out_f32 + outIdx, h);
                outIdx += strideO;
            }
        }
        __syncthreads();   // all reads of buf[cur] done before refill

        if (kk + SBUF < NP) {
            SCAN_PREFETCH(cur, K0 + kk + SBUF);
        }
    }
#undef SCAN_PREFETCH

    if (part == NPARTS - 1) {
        hf[lbd + d] = h;
        extraf[lb3d + 0 * DIM + d] = c;
        extraf[lb3d + 1 * DIM + d] = n;
        extraf[lb3d + 2 * DIM + d] = m;
    } else {
        state[0 * LANES + idx] = h;
        state[1 * LANES + idx] = c;
        state[2 * LANES + idx] = n;
        state[3 * LANES + idx] = m;
    }
}

// ---------------------------------------------------------------------------
// Launch. Inputs: input, h0, extra0, W0, b0, r0, W1, b1, r1
// Output: output[S,B,D] || h_f[L,B,D] || extra_f[L,B,3D]
// Pipelined: scan0 parts on default stream; GEMM1 M-slices on stream2, each
// gated on its scan0 part; scan1 parts on default, each gated on its slice.
// ---------------------------------------------------------------------------
extern "C" void kernel_launch(void* const* d_in, const int* in_sizes, int n_in,
                              void* d_out, int out_size)
{
    const float* input  = (const float*)d_in[0];
    const float* h0     = (const float*)d_in[1];
    const float* extra0 = (const float*)d_in[2];
    const float* W0     = (const float*)d_in[3];
    const float* b0     = (const float*)d_in[4];
    const float* r0     = (const float*)d_in[5];
    const float* W1     = (const float*)d_in[6];
    const float* b1     = (const float*)d_in[7];
    const float* r1     = (const float*)d_in[8];

    float* out    = (float*)d_out;
    float* hf     = out + (size_t)S_LEN * BATCH * DIM;
    float* extraf = hf + (size_t)2 * BATCH * DIM;

    __half* pre;  cudaGetSymbolAddress((void**)&pre, g_pre);
    __half* ah;   cudaGetSymbolAddress((void**)&ah,  g_ah);
    __half* wh0;  cudaGetSymbolAddress((void**)&wh0, g_wh0);
    __half* wh1;  cudaGetSymbolAddress((void**)&wh1, g_wh1);
    float* state; cudaGetSymbolAddress((void**)&state, g_state);

    cudaFuncSetAttribute(gemm_tc_kernel,
                         cudaFuncAttributeMaxDynamicSharedMemorySize, GEMM_SMEM);

    dim3 gemmGridFull(GDIM / 128, MROWS / 128);         // (32, 128)
    dim3 gemmGridSlice(GDIM / 128, MROWS / 128 / NPARTS); // (32, 32)
    dim3 scanGrid(LANES / 64);                          // 256
    const int MSLICE = MROWS / NPARTS;                  // 4096 rows

    // Fork stream2 off the capture origin.
    cudaEventRecord(g_evFork, 0);
    cudaStreamWaitEvent(g_s2, g_evFork, 0);

    // Converts: W1 on stream2 (only GEMM1 needs it); input+W0 on default.
    convert_kernel<<<NW_BLOCKS, 256, 0, g_s2>>>(W1, wh1);
    convert_kernel<<<NA_BLOCKS, 256>>>(input, ah);
    convert_kernel<<<NW_BLOCKS, 256>>>(W0, wh0);

    // GEMM0 (full) on default.
    gemm_tc_kernel<<<gemmGridFull, 128, GEMM_SMEM>>>(ah, wh0, pre, 0);

    // scan0 parts on default; each publishes an event.
    for (int i = 0; i < NPARTS; i++) {
        slstm_scan_kernel<true><<<scanGrid, 64>>>(
            pre, b0, r0, h0, extra0, 0, i, nullptr, ah, hf, extraf, state);
        cudaEventRecord(g_evS0[i], 0);
    }

    // GEMM1 M-slices on stream2, each gated on its scan0 part.
    for (int i = 0; i < NPARTS; i++) {
        cudaStreamWaitEvent(g_s2, g_evS0[i], 0);
        gemm_tc_kernel<<<gemmGridSlice, 128, GEMM_SMEM, g_s2>>>(
            ah, wh1, pre, i * MSLICE);
        cudaEventRecord(g_evG1[i], g_s2);
    }

    // scan1 parts on default, each gated on its GEMM1 slice (joins stream2).
    for (int i = 0; i < NPARTS; i++) {
        cudaStreamWaitEvent(0, g_evG1[i], 0);
        slstm_scan_kernel<false><<<scanGrid, 64>>>(
            pre, b1, r1, h0, extra0, 1, i, out, nullptr, hf, extraf, state);
    }
}

// round 17
// speedup vs baseline: 1.0338x; 1.0338x over previous
#include <cuda_runtime.h>
#include <cuda_fp16.h>
#include <math.h>
#include <stdint.h>

// Problem constants (fixed: S=1024, B=16, I=D=1024, L=2)
#define S_LEN 1024
#define BATCH 16
#define DIM   1024
#define GDIM  (4 * DIM)       // 4096
#define KDIM  1024
#define MROWS (S_LEN * BATCH) // 16384
#define EPS 1e-6f

// ---------------------------------------------------------------------------
// Device scratch (no allocation allowed in kernel_launch)
// ---------------------------------------------------------------------------
__device__ __half g_pre[(size_t)S_LEN * BATCH * GDIM];  // 134 MB (NO bias; fp16)
__device__ __half g_ah[(size_t)MROWS * KDIM];           // 33.5 MB (A in fp16)
__device__ __half g_wh0[(size_t)GDIM * KDIM];           // 8.4 MB  (W0 fp16)
__device__ __half g_wh1[(size_t)GDIM * KDIM];           // 8.4 MB  (W1 fp16)

// ---------------------------------------------------------------------------
// Host-side stream/events (created in a static initializer: no device-memory
// delta during the run; kernel_launch records the identical DAG every call).
// Stream2 carries ONLY the W1 convert — no dependency added to the critical
// path (R16 lesson: fine-grained producer/consumer overlap loses to wave
// quantization; only dependency-free work may ride a second stream).
// ---------------------------------------------------------------------------
static cudaStream_t g_s2;
static cudaEvent_t  g_evFork;
static cudaEvent_t  g_evW1;
static int g_init_dummy = [](){
    cudaStreamCreateWithFlags(&g_s2, cudaStreamNonBlocking);
    cudaEventCreateWithFlags(&g_evFork, cudaEventDisableTiming);
    cudaEventCreateWithFlags(&g_evW1,   cudaEventDisableTiming);
    return 0;
}();

// ---------------------------------------------------------------------------
// PTX helpers — base-target only (NO tcgen05: harness emits compute_103 PTX)
// ---------------------------------------------------------------------------
__device__ __forceinline__ uint32_t smem_u32(const void* p) {
    uint32_t a;
    asm("{ .reg .u64 t; cvta.to.shared.u64 t, %1; cvt.u32.u64 %0, t; }"
        : "=r"(a) : "l"(p));
    return a;
}
__device__ __forceinline__ void cp16(uint32_t dst, const void* src) {
    asm volatile("cp.async.cg.shared.global [%0], [%1], 16;"
                 :: "r"(dst), "l"(src));
}
__device__ __forceinline__ void ldsm_x4(uint32_t& r0, uint32_t& r1,
                                        uint32_t& r2, uint32_t& r3,
                                        uint32_t addr) {
    asm volatile("ldmatrix.sync.aligned.m8n8.x4.shared.b16 {%0,%1,%2,%3}, [%4];"
                 : "=r"(r0), "=r"(r1), "=r"(r2), "=r"(r3) : "r"(addr));
}
__device__ __forceinline__ void mma_f16(float* d, const uint32_t* a,
                                        uint32_t b0, uint32_t b1) {
    asm volatile(
        "mma.sync.aligned.m16n8k16.row.col.f32.f16.f16.f32 "
        "{%0,%1,%2,%3}, {%4,%5,%6,%7}, {%8,%9}, {%0,%1,%2,%3};"
        : "+f"(d[0]), "+f"(d[1]), "+f"(d[2]), "+f"(d[3])
        : "r"(a[0]), "r"(a[1]), "r"(a[2]), "r"(a[3]), "r"(b0), "r"(b1));
}

// Fast math (rel err ~2^-21; far under the 1e-3 budget)
__device__ __forceinline__ float fast_tanh(float x) {
    float e = __expf(2.0f * x);
    return __fdividef(e - 1.0f, e + 1.0f);
}

// Swizzle: rows are 64B (32 fp16); XOR the 16B-segment index with (row>>1)&3
__device__ __forceinline__ uint32_t swz_addr(uint32_t plane_base, int row, int seg) {
    return plane_base + (uint32_t)(row * 64) + ((uint32_t)((seg ^ ((row >> 1) & 3)) << 4));
}

// ---------------------------------------------------------------------------
// fp32 -> fp16 converts.
// convert_aw0: input (16384 blocks) + W0 (4096 blocks) fused, default stream.
// convert_kernel: generic (used for W1 on stream2).
// ---------------------------------------------------------------------------
#define NA_BLOCKS (MROWS * KDIM / 1024)   // 16384
#define NW_BLOCKS (GDIM * KDIM / 1024)    // 4096

__global__ __launch_bounds__(256)
void convert_aw0_kernel(const float* __restrict__ input,
                        const float* __restrict__ W0,
                        __half* __restrict__ ah,
                        __half* __restrict__ wh0)
{
    const float* src;
    __half* dst;
    int blk = blockIdx.x;
    if (blk < NA_BLOCKS) { src = input; dst = ah; }
    else                 { src = W0; dst = wh0; blk -= NA_BLOCKS; }

    int i = (blk * 256 + threadIdx.x) * 4;
    float4 v = __ldcs(reinterpret_cast<const float4*>(src + i));
    __half2* d2 = reinterpret_cast<__half2*>(dst + i);
    d2[0] = __half2(__float2half(v.x), __float2half(v.y));
    d2[1] = __half2(__float2half(v.z), __float2half(v.w));
}

__global__ __launch_bounds__(256)
void convert_kernel(const float* __restrict__ src, __half* __restrict__ dst)
{
    int i = (blockIdx.x * 256 + threadIdx.x) * 4;
    float4 v = __ldcs(reinterpret_cast<const float4*>(src + i));
    __half2* d2 = reinterpret_cast<__half2*>(dst + i);
    d2[0] = __half2(__float2half(v.x), __float2half(v.y));
    d2[1] = __half2(__float2half(v.z), __float2half(v.w));
}

// ---------------------------------------------------------------------------
// HMMA GEMM (R11/R14/R15 best config — DO NOT PERTURB): C[M,N] = A @ W^T,
// fp16 in/out, fp32 accum, NO bias. CTA 128x128, 4 warps (2Mx2N, 64x64 warp
// tiles), 128-thr CTAs, 2 CTAs/SM. K-chunk 32, 4-stage cp.async pipeline.
// ---------------------------------------------------------------------------
#define KCHUNK 32
#define NCHUNK (KDIM / KCHUNK)       // 32
#define PLANE  8192                  // 128 rows * 64 bytes
#define STAGE_BYTES (2 * PLANE)      // [A, W] = 16 KB
#define STAGES 4
#define GEMM_SMEM (STAGES * STAGE_BYTES)   // 64 KB

__device__ __forceinline__ void load_chunk(uint32_t stage_base,
                                           const __half* Ap,
                                           const __half* Wp,
                                           int k0, int tid)
{
    // 2 planes x 128 rows x 4 segs(16B) = 1024 cp16 / 128 threads = 8 each.
#pragma unroll
    for (int p = 0; p < 2; p++) {
        const __half* src = (p == 0) ? Ap : Wp;
#pragma unroll
        for (int h = 0; h < 4; h++) {
            int it = tid + h * 128;          // 0..511
            int row = it >> 2;
            int seg = it & 3;
            cp16(swz_addr(stage_base + p * PLANE, row, seg),
                 src + (size_t)row * KDIM + k0 + seg * 8);
        }
    }
}

__global__ __launch_bounds__(128, 2)
void gemm_tc_kernel(const __half* __restrict__ Ah,
                    const __half* __restrict__ Wh,
                    __half* __restrict__ C)
{
    extern __shared__ __align__(1024) char smem[];
    const uint32_t sbase = smem_u32(smem);
    const int tid  = threadIdx.x;
    const int wid  = tid >> 5;      // 0..3
    const int lane = tid & 31;
    const int warp_m = wid & 1;     // 2 warps in M: 64 rows each
    const int warp_n = wid >> 1;    // 2 warps in N: 64 cols each
    const int bm = blockIdx.y * 128;
    const int bn = blockIdx.x * 128;

    const __half* Ap = Ah + (size_t)bm * KDIM;
    const __half* Wp = Wh + (size_t)bn * KDIM;

    float acc[4][8][4];
#pragma unroll
    for (int i = 0; i < 4; i++)
#pragma unroll
        for (int j = 0; j < 8; j++)
#pragma unroll
            for (int k = 0; k < 4; k++) acc[i][j][k] = 0.0f;

    // Prologue: stages 0,1,2
    load_chunk(sbase + 0 * STAGE_BYTES, Ap, Wp, 0 * KCHUNK, tid);
    asm volatile("cp.async.commit_group;");
    load_chunk(sbase + 1 * STAGE_BYTES, Ap, Wp, 1 * KCHUNK, tid);
    asm volatile("cp.async.commit_group;");
    load_chunk(sbase + 2 * STAGE_BYTES, Ap, Wp, 2 * KCHUNK, tid);
    asm volatile("cp.async.commit_group;");

    const int a_lrow = lane & 15;
    const int a_lseg = lane >> 4;
    const int b_lrow = (lane & 7) + ((lane >> 4) << 3);
    const int b_lseg = (lane >> 3) & 1;

    for (int i = 0; i < NCHUNK; i++) {
        const int rem = NCHUNK - 1 - i;
        if (rem >= 2)      { asm volatile("cp.async.wait_group 2;"); }
        else if (rem == 1) { asm volatile("cp.async.wait_group 1;"); }
        else               { asm volatile("cp.async.wait_group 0;"); }
        __syncthreads();

        if (i + 3 < NCHUNK) {
            load_chunk(sbase + (uint32_t)((i + 3) % STAGES) * STAGE_BYTES,
                       Ap, Wp, (i + 3) * KCHUNK, tid);
            asm volatile("cp.async.commit_group;");
        }

        const uint32_t st = sbase + (uint32_t)(i % STAGES) * STAGE_BYTES;
        const uint32_t base_a = st;
        const uint32_t base_w = st + PLANE;

#pragma unroll
        for (int ks = 0; ks < 2; ks++) {
            uint32_t a[4][4], w[4][4];
#pragma unroll
            for (int jj = 0; jj < 4; jj++) {
                int row = warp_n * 64 + jj * 16 + b_lrow;
                ldsm_x4(w[jj][0], w[jj][1], w[jj][2], w[jj][3],
                        swz_addr(base_w, row, ks * 2 + b_lseg));
            }
#pragma unroll
            for (int ti = 0; ti < 4; ti++) {
                int row = warp_m * 64 + ti * 16 + a_lrow;
                ldsm_x4(a[ti][0], a[ti][1], a[ti][2], a[ti][3],
                        swz_addr(base_a, row, ks * 2 + a_lseg));
            }
#pragma unroll
            for (int ti = 0; ti < 4; ti++)
#pragma unroll
                for (int jj = 0; jj < 4; jj++) {
                    mma_f16(acc[ti][2 * jj + 0], a[ti], w[jj][0], w[jj][1]);
                    mma_f16(acc[ti][2 * jj + 1], a[ti], w[jj][2], w[jj][3]);
                }
        }
    }

    // Epilogue: fp16 streaming stores (C read once by the scan; 134MB)
    const int mrow0 = bm + warp_m * 64 + (lane >> 2);
    const int col0  = bn + warp_n * 64 + (lane & 3) * 2;
#pragma unroll
    for (int ti = 0; ti < 4; ti++) {
        const int r0 = mrow0 + ti * 16;
#pragma unroll
        for (int g = 0; g < 8; g++) {
            int col = col0 + g * 8;
            __half2 v0 = __floats2half2_rn(acc[ti][g][0], acc[ti][g][1]);
            __half2 v1 = __floats2half2_rn(acc[ti][g][2], acc[ti][g][3]);
            __stcs(reinterpret_cast<__half2*>(C + (size_t)r0 * GDIM + col), v0);
            __stcs(reinterpret_cast<__half2*>(C + (size_t)(r0 + 8) * GDIM + col), v1);
        }
    }
}

// ---------------------------------------------------------------------------
// Elementwise sLSTM scan (R15): fp16 pre (bias-free) staged via cp.async,
// quad buffered; bias added in fp32; MUFU reductions (exp-min select +
// fused sigmoid/normalizer divide).
// EMIT_HALF: layer-0 writes h as fp16 into ah (GEMM1's A operand).
// ---------------------------------------------------------------------------
#define CH 16
#define NCH (S_LEN / CH)   // 64 chunks
#define SBUF 4

template <bool EMIT_HALF>
__global__ __launch_bounds__(64)
void slstm_scan_kernel(const __half* __restrict__ pre,    // [S,B,4D] (no bias)
                       const float* __restrict__ bias,    // [4D]
                       const float* __restrict__ r,       // [4D]
                       const float* __restrict__ h0,      // [L,B,D]
                       const float* __restrict__ extra0,  // [L,B,3D]
                       int layer,
                       float* __restrict__ out_f32,       // [S,B,D] (or null)
                       __half* __restrict__ out_h16,      // [S,B,D] (or null)
                       float* __restrict__ hf,            // [L,B,D]
                       float* __restrict__ extraf)        // [L,B,3D]
{
    __shared__ __half buf[SBUF][CH][4][64];   // 16 KB

    const int ltid = threadIdx.x;                 // 0..63
    const int L0 = blockIdx.x * 64;               // lane base (all same b)
    const int b  = L0 >> 10;
    const int d0 = L0 & (DIM - 1);
    const int d  = d0 + ltid;

    const float rz = r[0 * DIM + d];
    const float ri = r[1 * DIM + d];
    const float rf = r[2 * DIM + d];
    const float ro = r[3 * DIM + d];
    const float bz = bias[0 * DIM + d];
    const float bi = bias[1 * DIM + d];
    const float bf = bias[2 * DIM + d];
    const float bo = bias[3 * DIM + d];
    const bool rzero = (rz == 0.0f) && (ri == 0.0f) && (rf == 0.0f) && (ro == 0.0f);

    const size_t lbd  = (size_t)layer * BATCH * DIM + (size_t)b * DIM;
    const size_t lb3d = (size_t)layer * BATCH * 3 * DIM + (size_t)b * 3 * DIM;

    float h = h0[lbd + d];
    float c = extra0[lb3d + 0 * DIM + d];
    float n = extra0[lb3d + 1 * DIM + d];
    float m = extra0[lb3d + 2 * DIM + d];

    // Prefetch mapping: g = gate (0..3), cc = 16B chunk (0..7), sh = parity.
    const int g  = ltid >> 4;
    const int cc = ltid & 7;
    const int sh = (ltid >> 3) & 1;
    const size_t strideT = (size_t)BATCH * GDIM;
    const __half* src0 = pre + (size_t)b * GDIM + (size_t)g * DIM + d0 + cc * 8;

#define SCAN_PREFETCH(stage, k)                                               \
    do {                                                                      \
        const __half* _s = src0 + ((size_t)(k) * CH + sh) * strideT;          \
        _Pragma("unroll")                                                     \
        for (int _jj = 0; _jj < CH / 2; _jj++) {                              \
            cp16(smem_u32(&buf[stage][2 * _jj + sh][g][cc * 8]), _s);         \
            _s += 2 * strideT;                                                \
        }                                                                     \
        asm volatile("cp.async.commit_group;");                               \
    } while (0)

    SCAN_PREFETCH(0, 0);
    SCAN_PREFETCH(1, 1);
    SCAN_PREFETCH(2, 2);
    SCAN_PREFETCH(3, 3);

    size_t outIdx = (size_t)b * DIM + d;
    const size_t strideO = (size_t)BATCH * DIM;

    for (int k = 0; k < NCH; k++) {
        if (k + 3 < NCH)      { asm volatile("cp.async.wait_group 3;"); }
        else if (k + 2 < NCH) { asm volatile("cp.async.wait_group 2;"); }
        else if (k + 1 < NCH) { asm volatile("cp.async.wait_group 1;"); }
        else                  { asm volatile("cp.async.wait_group 0;"); }
        __syncthreads();

        const int cur = k % SBUF;

        if (rzero) {
            // Batch phase (full ILP): zt = tanh(z_pre), den = 1 + exp(-o_pre).
            float zt[CH], den[CH];
#pragma unroll
            for (int j = 0; j < CH; j++) {
                zt[j]  = fast_tanh(__half2float(buf[cur][j][0][ltid]) + bz);
                den[j] = 1.0f + __expf(-(__half2float(buf[cur][j][3][ltid]) + bo));
            }
            // Serial phase: 2 MUFU/step (exp-min + fused divide).
#pragma unroll
            for (int j = 0; j < CH; j++) {
                const float ip = __half2float(buf[cur][j][1][ltid]) + bi;
                const float fm = __half2float(buf[cur][j][2][ltid]) + bf + m;
                const float mn = fmaxf(fm, ip);
                const float e  = __expf(fminf(fm, ip) - mn);
                const bool ffl = fm >= ip;
                const float ft = ffl ? 1.0f : e;
                const float it = ffl ? e : 1.0f;
                c = ft * c + it * zt[j];
                n = ft * n + it;
                m = mn;
                h = __fdividef(c, den[j] * (fabsf(n) + EPS));
                if (EMIT_HALF) out_h16[outIdx] = __float2half(h);
                else           __stcs(out_f32 + outIdx, h);
                outIdx += strideO;
            }
        } else {
#pragma unroll
            for (int j = 0; j < CH; j++) {
                const float zp = __half2float(buf[cur][j][0][ltid]) + bz + rz * h;
                const float ip = __half2float(buf[cur][j][1][ltid]) + bi + ri * h;
                const float fp = __half2float(buf[cur][j][2][ltid]) + bf + rf * h;
                const float op = __half2float(buf[cur][j][3][ltid]) + bo + ro * h;
                const float zt  = fast_tanh(zp);
                const float den = 1.0f + __expf(-op);
                const float fm = fp + m;
                const float mn = fmaxf(fm, ip);
                const float e  = __expf(fminf(fm, ip) - mn);
                const bool ffl = fm >= ip;
                const float ft = ffl ? 1.0f : e;
                const float it = ffl ? e : 1.0f;
                c = ft * c + it * zt;
                n = ft * n + it;
                m = mn;
                h = __fdividef(c, den * (fabsf(n) + EPS));
                if (EMIT_HALF) out_h16[outIdx] = __float2half(h);
                else           __stcs(out_f32 + outIdx, h);
                outIdx += strideO;
            }
        }
        __syncthreads();   // all reads of buf[cur] done before refill

        if (k + SBUF < NCH) {
            SCAN_PREFETCH(cur, k + SBUF);
        }
    }
#undef SCAN_PREFETCH

    hf[lbd + d] = h;
    extraf[lb3d + 0 * DIM + d] = c;
    extraf[lb3d + 1 * DIM + d] = n;
    extraf[lb3d + 2 * DIM + d] = m;
}

// ---------------------------------------------------------------------------
// Launch. Inputs: input, h0, extra0, W0, b0, r0, W1, b1, r1
// Output: output[S,B,D] || h_f[L,B,D] || extra_f[L,B,3D]
// W1 convert rides stream2 (dependency-free), overlapping convert+GEMM0.
// ---------------------------------------------------------------------------
extern "C" void kernel_launch(void* const* d_in, const int* in_sizes, int n_in,
                              void* d_out, int out_size)
{
    const float* input  = (const float*)d_in[0];
    const float* h0     = (const float*)d_in[1];
    const float* extra0 = (const float*)d_in[2];
    const float* W0     = (const float*)d_in[3];
    const float* b0     = (const float*)d_in[4];
    const float* r0     = (const float*)d_in[5];
    const float* W1     = (const float*)d_in[6];
    const float* b1     = (const float*)d_in[7];
    const float* r1     = (const float*)d_in[8];

    float* out    = (float*)d_out;
    float* hf     = out + (size_t)S_LEN * BATCH * DIM;
    float* extraf = hf + (size_t)2 * BATCH * DIM;

    __half* pre;  cudaGetSymbolAddress((void**)&pre, g_pre);
    __half* ah;   cudaGetSymbolAddress((void**)&ah,  g_ah);
    __half* wh0;  cudaGetSymbolAddress((void**)&wh0, g_wh0);
    __half* wh1;  cudaGetSymbolAddress((void**)&wh1, g_wh1);

    cudaFuncSetAttribute(gemm_tc_kernel,
                         cudaFuncAttributeMaxDynamicSharedMemorySize, GEMM_SMEM);

    dim3 gemmGrid(GDIM / 128, MROWS / 128);   // (32, 128) = 4096 CTAs
    dim3 scanGrid((BATCH * DIM) / 64);        // 256

    // Fork stream2; W1 convert overlaps the default-stream convert + GEMM0.
    cudaEventRecord(g_evFork, 0);
    cudaStreamWaitEvent(g_s2, g_evFork, 0);
    convert_kernel<<<NW_BLOCKS, 256, 0, g_s2>>>(W1, wh1);
    cudaEventRecord(g_evW1, g_s2);

    // input + W0 converts fused, default stream.
    convert_aw0_kernel<<<NA_BLOCKS + NW_BLOCKS, 256>>>(input, W0, ah, wh0);

    // ---- Layer 0 ----
    gemm_tc_kernel<<<gemmGrid, 128, GEMM_SMEM>>>(ah, wh0, pre);
    slstm_scan_kernel<true><<<scanGrid, 64>>>(pre, b0, r0, h0, extra0, 0,
                                              nullptr, ah, hf, extraf);

    // ---- Layer 1 (join W1 convert) ----
    cudaStreamWaitEvent(0, g_evW1, 0);
    gemm_tc_kernel<<<gemmGrid, 128, GEMM_SMEM>>>(ah, wh1, pre);
    slstm_scan_kernel<false><<<scanGrid, 64>>>(pre, b1, r1, h0, extra0, 1,
                                               out, nullptr, hf, extraf);
}